// round 12
// baseline (speedup 1.0000x reference)
#include <cuda_runtime.h>
#include <cuda_fp16.h>
#include <cstdint>

#define N_LEVELS 16
#define N_FEAT 2
#define LOG2_HASHMAP 19
#define HASHMAP_SIZE (1u << LOG2_HASHMAP)
#define HASH_MASK (HASHMAP_SIZE - 1u)

// Levels 0..8 get dense fp16 face-packed tables.
#define N_DENSE 9
#define DENSE_TOTAL 2081036   // sum over R of (R+1)*R*R entries (16B each) = 33.3MB
#define FSCALE 8192.0f
#define INV_FSCALE (1.0f / 8192.0f)
#define BUILD_WARPS 10883
#define BUILD_THREADS (BUILD_WARPS * 32)

// floor(16 * (512/16)^(l/15)) computed in exact real arithmetic.
__constant__ float c_res[N_LEVELS] = {
    16.f, 20.f, 25.f, 32.f, 40.f, 50.f, 64.f, 80.f,
    101.f, 128.f, 161.f, 203.f, 256.f, 322.f, 406.f, 512.f
};
__constant__ int c_resi[N_DENSE] = {16, 20, 25, 32, 40, 50, 64, 80, 101};
// entry offsets (16B units) per dense level
__constant__ int c_eoff[N_DENSE + 1] = {
    0, 4352, 12752, 29002, 62794, 128394, 255894, 522134, 1040534, 2081036
};
__constant__ int c_kcn[N_DENSE] = {2, 3, 4, 4, 5, 7, 8, 10, 13};  // ceil(R/8)
__constant__ int c_jw[N_DENSE]  = {1, 1, 1, 2, 2, 2, 3, 3, 4};    // ceil(R/31)
// warp-id offsets per level: cumsum of (R+1)*JW*KC
__constant__ int c_woff[N_DENSE + 1] = {
    0, 34, 97, 201, 465, 875, 1589, 3149, 5579, 10883
};

// Face-packed dense tables. Entry E(i,j,k), idx = eoff + (i*R + k)*R + j:
//   bytes [0:8)  = fp16x4 of corners (i,j,k),(i,j,k+1)     (feat0,feat1 each)
//   bytes [8:16) = fp16x4 of corners (i,j+1,k),(i,j+1,k+1)
__device__ uint4 g_dense[DENSE_TOTAL];

__device__ __forceinline__ uint32_t hprod_y(uint32_t v) { return v * 2654435761u; }
__device__ __forceinline__ uint32_t hprod_z(uint32_t v) { return v * 805459861u; }

// ---------------- prologue: shuffle builder, coalesced 16B stores ----------------
__global__ __launch_bounds__(256) void build_dense_kernel(const float2* __restrict__ table)
{
    int gtid = blockIdx.x * blockDim.x + threadIdx.x;
    int w    = gtid >> 5;
    int lane = gtid & 31;
    if (w >= BUILD_WARPS) return;

    int l = 0;
    #pragma unroll
    for (int t = 1; t < N_DENSE; t++)
        if (w >= c_woff[t]) l = t;

    int local = w - c_woff[l];
    int R  = c_resi[l];
    int KC = c_kcn[l];
    int JW = c_jw[l];

    int kc = local % KC;
    int t2 = local / KC;
    int jw = t2 % JW;
    int i  = t2 / JW;

    int j  = jw * 31 + lane;
    int jc = min(j, R);
    int k0   = kc * 8;
    int kend = min(k0 + 8, R);

    const float2* tl = table + (size_t)l * HASHMAP_SIZE;
    uint32_t hxy = (uint32_t)i ^ hprod_y((uint32_t)jc);

    float2 prev = __ldg(&tl[(hxy ^ hprod_z((uint32_t)k0)) & HASH_MASK]);

    bool do_store = (lane < 31) && (j < R);
    int ebase = c_eoff[l] + i * R * R + j;

    for (int k = k0; k < kend; k++) {
        float2 cur = __ldg(&tl[(hxy ^ hprod_z((uint32_t)(k + 1))) & HASH_MASK]);
        half2 h0 = __floats2half2_rn(prev.x * FSCALE, prev.y * FSCALE);
        half2 h1 = __floats2half2_rn(cur.x * FSCALE, cur.y * FSCALE);
        uint32_t lo = *reinterpret_cast<uint32_t*>(&h0);
        uint32_t hi = *reinterpret_cast<uint32_t*>(&h1);
        uint32_t nlo = __shfl_down_sync(0xffffffffu, lo, 1);
        uint32_t nhi = __shfl_down_sync(0xffffffffu, hi, 1);
        if (do_store)
            g_dense[ebase + k * R] = make_uint4(lo, hi, nlo, nhi);
        prev = cur;
    }
}

// ---------------- main kernel ----------------
// Block = 512 threads = 16 warps; warp w handles level w for 32 consecutive points.
// Division-free coords (valid by trilerp continuity across voxel boundaries).
// Output transposed through smem for fully coalesced streaming stores.
__global__ __launch_bounds__(512) void ngp_embed_kernel(
    const float* __restrict__ x,
    const float2* __restrict__ table,
    float* __restrict__ out,
    int B)
{
    __shared__ float sx[96];          // 32 points * 3 coords
    __shared__ float so[32 * 33];     // transpose buffer, padded stride 33

    int lane = threadIdx.x & 31;
    int l    = threadIdx.x >> 5;      // level = warp id
    int b0   = blockIdx.x * 32;

    if (threadIdx.x < 96) {
        int gi = b0 * 3 + threadIdx.x;
        sx[threadIdx.x] = (gi < B * 3) ? x[gi] : 0.0f;
    }
    __syncthreads();

    float px = sx[lane * 3 + 0];
    float py = sx[lane * 3 + 1];
    float pz = sx[lane * 3 + 2];

    float res = c_res[l];
    float fx = px * res;
    float fy = py * res;
    float fz = pz * res;
    int bx = (int)fx;
    int by = (int)fy;
    int bz = (int)fz;
    float wx = fx - (float)bx;
    float wy = fy - (float)by;
    float wz = fz - (float)bz;

    float v000x, v000y, v001x, v001y, v010x, v010y, v011x, v011y;
    float v100x, v100y, v101x, v101y, v110x, v110y, v111x, v111y;
    float sc;

    if (l < N_DENSE) {
        // Dense fp16 face-packed path: 2 x 16B gathers for all 8 corners.
        int R = (int)res;
        int eidx = c_eoff[l] + (bx * R + bz) * R + by;

        uint4 e0 = __ldg(&g_dense[eidx]);          // x-plane bx
        uint4 e1 = __ldg(&g_dense[eidx + R * R]);  // x-plane bx+1

        float2 f;
        f = __half22float2(*reinterpret_cast<half2*>(&e0.x)); v000x = f.x; v000y = f.y;
        f = __half22float2(*reinterpret_cast<half2*>(&e0.y)); v001x = f.x; v001y = f.y;
        f = __half22float2(*reinterpret_cast<half2*>(&e0.z)); v010x = f.x; v010y = f.y;
        f = __half22float2(*reinterpret_cast<half2*>(&e0.w)); v011x = f.x; v011y = f.y;
        f = __half22float2(*reinterpret_cast<half2*>(&e1.x)); v100x = f.x; v100y = f.y;
        f = __half22float2(*reinterpret_cast<half2*>(&e1.y)); v101x = f.x; v101y = f.y;
        f = __half22float2(*reinterpret_cast<half2*>(&e1.z)); v110x = f.x; v110y = f.y;
        f = __half22float2(*reinterpret_cast<half2*>(&e1.w)); v111x = f.x; v111y = f.y;
        sc = INV_FSCALE;
    } else {
        // Hashed path: 8 x float2 gathers.
        uint32_t hx0 = (uint32_t)bx;
        uint32_t hx1 = (uint32_t)(bx + 1);
        uint32_t hy0 = hprod_y((uint32_t)by);
        uint32_t hy1 = hprod_y((uint32_t)(by + 1));
        uint32_t hz0 = hprod_z((uint32_t)bz);
        uint32_t hz1 = hprod_z((uint32_t)(bz + 1));

        const float2* tl = table + (size_t)l * HASHMAP_SIZE;

        float2 v000 = __ldg(&tl[(hx0 ^ hy0 ^ hz0) & HASH_MASK]);
        float2 v001 = __ldg(&tl[(hx0 ^ hy0 ^ hz1) & HASH_MASK]);
        float2 v010 = __ldg(&tl[(hx0 ^ hy1 ^ hz0) & HASH_MASK]);
        float2 v011 = __ldg(&tl[(hx0 ^ hy1 ^ hz1) & HASH_MASK]);
        float2 v100 = __ldg(&tl[(hx1 ^ hy0 ^ hz0) & HASH_MASK]);
        float2 v101 = __ldg(&tl[(hx1 ^ hy0 ^ hz1) & HASH_MASK]);
        float2 v110 = __ldg(&tl[(hx1 ^ hy1 ^ hz0) & HASH_MASK]);
        float2 v111 = __ldg(&tl[(hx1 ^ hy1 ^ hz1) & HASH_MASK]);

        v000x = v000.x; v000y = v000.y; v001x = v001.x; v001y = v001.y;
        v010x = v010.x; v010y = v010.y; v011x = v011.x; v011y = v011.y;
        v100x = v100.x; v100y = v100.y; v101x = v101.x; v101y = v101.y;
        v110x = v110.x; v110y = v110.y; v111x = v111.x; v111y = v111.y;
        sc = 1.0f;
    }

    float omx = 1.0f - wx, omy = 1.0f - wy, omz = 1.0f - wz;

    float c00_0 = v000x * omx + v100x * wx;
    float c00_1 = v000y * omx + v100y * wx;
    float c01_0 = v001x * omx + v101x * wx;
    float c01_1 = v001y * omx + v101y * wx;
    float c10_0 = v010x * omx + v110x * wx;
    float c10_1 = v010y * omx + v110y * wx;
    float c11_0 = v011x * omx + v111x * wx;
    float c11_1 = v011y * omx + v111y * wx;

    float c0_0 = c00_0 * omy + c10_0 * wy;
    float c0_1 = c00_1 * omy + c10_1 * wy;
    float c1_0 = c01_0 * omy + c11_0 * wy;
    float c1_1 = c01_1 * omy + c11_1 * wy;

    float r0 = (c0_0 * omz + c1_0 * wz) * sc;
    float r1 = (c0_1 * omz + c1_1 * wz) * sc;

    // transpose via smem (conflict-free: stride 33)
    so[lane * 33 + l]      = r0;
    so[lane * 33 + 16 + l] = r1;
    __syncthreads();

    int lim = (B - b0) * 32;
    if (lim > 1024) lim = 1024;
    float* orow = out + (size_t)b0 * 32;
    for (int t = threadIdx.x; t < lim; t += 512) {
        int row = t >> 5, col = t & 31;
        __stcs(orow + t, so[row * 33 + col]);
    }
}

extern "C" void kernel_launch(void* const* d_in, const int* in_sizes, int n_in,
                              void* d_out, int out_size)
{
    const float*  x     = (const float*)d_in[0];
    const float2* table = (const float2*)d_in[1];
    float*        out   = (float*)d_out;

    int B = in_sizes[0] / 3;

    build_dense_kernel<<<(BUILD_THREADS + 255) / 256, 256>>>(table);

    int grid = (B + 31) / 32;
    ngp_embed_kernel<<<grid, 512>>>(x, table, out, B);
}

// round 15
// speedup vs baseline: 1.1416x; 1.1416x over previous
#include <cuda_runtime.h>
#include <cuda_fp16.h>
#include <cstdint>

#define N_LEVELS 16
#define N_FEAT 2
#define LOG2_HASHMAP 19
#define HASHMAP_SIZE (1u << LOG2_HASHMAP)
#define HASH_MASK (HASHMAP_SIZE - 1u)

// Levels 0..8 get dense fp16 face-packed tables.
#define N_DENSE 9
#define DENSE_TOTAL 2081036   // sum over R of (R+1)*R*R entries (16B each) = 33.3MB
#define FSCALE 8192.0f
#define INV_FSCALE (1.0f / 8192.0f)
#define BUILD_WARPS 10883
#define BUILD_THREADS (BUILD_WARPS * 32)

// floor(16 * (512/16)^(l/15)) computed in exact real arithmetic.
__constant__ float c_res[N_LEVELS] = {
    16.f, 20.f, 25.f, 32.f, 40.f, 50.f, 64.f, 80.f,
    101.f, 128.f, 161.f, 203.f, 256.f, 322.f, 406.f, 512.f
};
__constant__ int c_resi[N_DENSE] = {16, 20, 25, 32, 40, 50, 64, 80, 101};
// entry offsets (16B units) per dense level
__constant__ int c_eoff[N_DENSE + 1] = {
    0, 4352, 12752, 29002, 62794, 128394, 255894, 522134, 1040534, 2081036
};
__constant__ int c_kcn[N_DENSE] = {2, 3, 4, 4, 5, 7, 8, 10, 13};  // ceil(R/8)
__constant__ int c_jw[N_DENSE]  = {1, 1, 1, 2, 2, 2, 3, 3, 4};    // ceil(R/31)
// warp-id offsets per level: cumsum of (R+1)*JW*KC
__constant__ int c_woff[N_DENSE + 1] = {
    0, 34, 97, 201, 465, 875, 1589, 3149, 5579, 10883
};

// Face-packed dense tables. Entry E(i,j,k), idx = eoff + (i*R + k)*R + j:
//   bytes [0:8)  = fp16x4 of corners (i,j,k),(i,j,k+1)     (feat0,feat1 each)
//   bytes [8:16) = fp16x4 of corners (i,j+1,k),(i,j+1,k+1)
__device__ uint4 g_dense[DENSE_TOTAL];

__device__ __forceinline__ uint32_t hprod_y(uint32_t v) { return v * 2654435761u; }
__device__ __forceinline__ uint32_t hprod_z(uint32_t v) { return v * 805459861u; }

// ---------------- prologue: shuffle builder, coalesced 16B stores ----------------
__global__ __launch_bounds__(256) void build_dense_kernel(const float2* __restrict__ table)
{
    int gtid = blockIdx.x * blockDim.x + threadIdx.x;
    int w    = gtid >> 5;
    int lane = gtid & 31;
    if (w >= BUILD_WARPS) return;

    int l = 0;
    #pragma unroll
    for (int t = 1; t < N_DENSE; t++)
        if (w >= c_woff[t]) l = t;

    int local = w - c_woff[l];
    int R  = c_resi[l];
    int KC = c_kcn[l];
    int JW = c_jw[l];

    int kc = local % KC;
    int t2 = local / KC;
    int jw = t2 % JW;
    int i  = t2 / JW;

    int j  = jw * 31 + lane;
    int jc = min(j, R);
    int k0   = kc * 8;
    int kend = min(k0 + 8, R);

    const float2* tl = table + (size_t)l * HASHMAP_SIZE;
    uint32_t hxy = (uint32_t)i ^ hprod_y((uint32_t)jc);

    float2 prev = __ldg(&tl[(hxy ^ hprod_z((uint32_t)k0)) & HASH_MASK]);

    bool do_store = (lane < 31) && (j < R);
    int ebase = c_eoff[l] + i * R * R + j;

    for (int k = k0; k < kend; k++) {
        float2 cur = __ldg(&tl[(hxy ^ hprod_z((uint32_t)(k + 1))) & HASH_MASK]);
        half2 h0 = __floats2half2_rn(prev.x * FSCALE, prev.y * FSCALE);
        half2 h1 = __floats2half2_rn(cur.x * FSCALE, cur.y * FSCALE);
        uint32_t lo = *reinterpret_cast<uint32_t*>(&h0);
        uint32_t hi = *reinterpret_cast<uint32_t*>(&h1);
        uint32_t nlo = __shfl_down_sync(0xffffffffu, lo, 1);
        uint32_t nhi = __shfl_down_sync(0xffffffffu, hi, 1);
        if (do_store)
            g_dense[ebase + k * R] = make_uint4(lo, hi, nlo, nhi);
        prev = cur;
    }
}

// ---------------- main kernel ----------------
// Thread = (point, level); levels interleaved within each warp -> uniform per-warp
// work, no barriers. Division-free coords (valid by trilerp continuity).
__global__ __launch_bounds__(256) void ngp_embed_kernel(
    const float* __restrict__ x,
    const float2* __restrict__ table,
    float* __restrict__ out,
    int B)
{
    int gid = blockIdx.x * blockDim.x + threadIdx.x;
    int b = gid >> 4;       // point index
    int l = gid & 15;       // level index
    if (b >= B) return;

    float px = __ldg(&x[3 * b + 0]);
    float py = __ldg(&x[3 * b + 1]);
    float pz = __ldg(&x[3 * b + 2]);

    float res = c_res[l];
    float fx = px * res;
    float fy = py * res;
    float fz = pz * res;
    int bx = (int)fx;
    int by = (int)fy;
    int bz = (int)fz;
    float wx = fx - (float)bx;
    float wy = fy - (float)by;
    float wz = fz - (float)bz;

    float v000x, v000y, v001x, v001y, v010x, v010y, v011x, v011y;
    float v100x, v100y, v101x, v101y, v110x, v110y, v111x, v111y;
    float sc;

    if (l < N_DENSE) {
        // Dense fp16 face-packed path: 2 x 16B gathers for all 8 corners.
        int R = (int)res;
        int eidx = c_eoff[l] + (bx * R + bz) * R + by;

        uint4 e0 = __ldg(&g_dense[eidx]);          // x-plane bx
        uint4 e1 = __ldg(&g_dense[eidx + R * R]);  // x-plane bx+1

        float2 f;
        f = __half22float2(*reinterpret_cast<half2*>(&e0.x)); v000x = f.x; v000y = f.y;
        f = __half22float2(*reinterpret_cast<half2*>(&e0.y)); v001x = f.x; v001y = f.y;
        f = __half22float2(*reinterpret_cast<half2*>(&e0.z)); v010x = f.x; v010y = f.y;
        f = __half22float2(*reinterpret_cast<half2*>(&e0.w)); v011x = f.x; v011y = f.y;
        f = __half22float2(*reinterpret_cast<half2*>(&e1.x)); v100x = f.x; v100y = f.y;
        f = __half22float2(*reinterpret_cast<half2*>(&e1.y)); v101x = f.x; v101y = f.y;
        f = __half22float2(*reinterpret_cast<half2*>(&e1.z)); v110x = f.x; v110y = f.y;
        f = __half22float2(*reinterpret_cast<half2*>(&e1.w)); v111x = f.x; v111y = f.y;
        sc = INV_FSCALE;
    } else {
        // Hashed path: 8 x float2 gathers.
        uint32_t hx0 = (uint32_t)bx;
        uint32_t hx1 = (uint32_t)(bx + 1);
        uint32_t hy0 = hprod_y((uint32_t)by);
        uint32_t hy1 = hprod_y((uint32_t)(by + 1));
        uint32_t hz0 = hprod_z((uint32_t)bz);
        uint32_t hz1 = hprod_z((uint32_t)(bz + 1));

        const float2* tl = table + (size_t)l * HASHMAP_SIZE;

        float2 v000 = __ldg(&tl[(hx0 ^ hy0 ^ hz0) & HASH_MASK]);
        float2 v001 = __ldg(&tl[(hx0 ^ hy0 ^ hz1) & HASH_MASK]);
        float2 v010 = __ldg(&tl[(hx0 ^ hy1 ^ hz0) & HASH_MASK]);
        float2 v011 = __ldg(&tl[(hx0 ^ hy1 ^ hz1) & HASH_MASK]);
        float2 v100 = __ldg(&tl[(hx1 ^ hy0 ^ hz0) & HASH_MASK]);
        float2 v101 = __ldg(&tl[(hx1 ^ hy0 ^ hz1) & HASH_MASK]);
        float2 v110 = __ldg(&tl[(hx1 ^ hy1 ^ hz0) & HASH_MASK]);
        float2 v111 = __ldg(&tl[(hx1 ^ hy1 ^ hz1) & HASH_MASK]);

        v000x = v000.x; v000y = v000.y; v001x = v001.x; v001y = v001.y;
        v010x = v010.x; v010y = v010.y; v011x = v011.x; v011y = v011.y;
        v100x = v100.x; v100y = v100.y; v101x = v101.x; v101y = v101.y;
        v110x = v110.x; v110y = v110.y; v111x = v111.x; v111y = v111.y;
        sc = 1.0f;
    }

    float omx = 1.0f - wx, omy = 1.0f - wy, omz = 1.0f - wz;

    float c00_0 = v000x * omx + v100x * wx;
    float c00_1 = v000y * omx + v100y * wx;
    float c01_0 = v001x * omx + v101x * wx;
    float c01_1 = v001y * omx + v101y * wx;
    float c10_0 = v010x * omx + v110x * wx;
    float c10_1 = v010y * omx + v110y * wx;
    float c11_0 = v011x * omx + v111x * wx;
    float c11_1 = v011y * omx + v111y * wx;

    float c0_0 = c00_0 * omy + c10_0 * wy;
    float c0_1 = c00_1 * omy + c10_1 * wy;
    float c1_0 = c01_0 * omy + c11_0 * wy;
    float c1_1 = c01_1 * omy + c11_1 * wy;

    float r0 = (c0_0 * omz + c1_0 * wz) * sc;
    float r1 = (c0_1 * omz + c1_1 * wz) * sc;

    // Streaming stores: don't let the 64MB output stream evict the table in L2.
    __stcs(&out[b * (N_FEAT * N_LEVELS) + l], r0);
    __stcs(&out[b * (N_FEAT * N_LEVELS) + 16 + l], r1);
}

extern "C" void kernel_launch(void* const* d_in, const int* in_sizes, int n_in,
                              void* d_out, int out_size)
{
    const float*  x     = (const float*)d_in[0];
    const float2* table = (const float2*)d_in[1];
    float*        out   = (float*)d_out;

    int B = in_sizes[0] / 3;

    build_dense_kernel<<<(BUILD_THREADS + 255) / 256, 256>>>(table);

    int total = B * N_LEVELS;
    int block = 256;
    int grid = (total + block - 1) / block;
    ngp_embed_kernel<<<grid, block>>>(x, table, out, B);
}